// round 1
// baseline (speedup 1.0000x reference)
#include <cuda_runtime.h>
#include <math.h>

#define BB   8
#define SS   2048
#define DD   768
#define HH   8
#define HDIM 96
#define M_ROWS (BB*SS)

// Scratch (allocation-free rule: __device__ globals)
__device__ float g_QKV[3][(size_t)BB*HH*SS*HDIM]; // Q,K,V in [B,H,S,HD]
__device__ float g_C[(size_t)BB*SS*DD];           // attention context [B,S,D]

// ---------------------------------------------------------------------------
// Kernel 1: fused QKV projection.  Y = X @ W^T + b, written in [B,H,S,HD].
// grid = (DD/64, M_ROWS/64, 3), block = 256. 64x64 tile, 4x4 microtile.
// ---------------------------------------------------------------------------
__global__ void __launch_bounds__(256) qkv_gemm_kernel(
    const float* __restrict__ X,
    const float* __restrict__ Wq, const float* __restrict__ bq,
    const float* __restrict__ Wk, const float* __restrict__ bk,
    const float* __restrict__ Wv, const float* __restrict__ bv)
{
    __shared__ float Xs[64][33];
    __shared__ float Ws[64][33];

    const int z = blockIdx.z;
    const float* __restrict__ W    = (z == 0) ? Wq : ((z == 1) ? Wk : Wv);
    const float* __restrict__ bias = (z == 0) ? bq : ((z == 1) ? bk : bv);
    float* __restrict__ outp = g_QKV[z];

    const int n0 = blockIdx.x * 64;
    const int m0 = blockIdx.y * 64;
    const int t  = threadIdx.x;
    const int tx = t & 15;   // 16 column-microtiles
    const int ty = t >> 4;   // 16 row-microtiles

    float acc[4][4];
#pragma unroll
    for (int i = 0; i < 4; i++)
#pragma unroll
        for (int j = 0; j < 4; j++) acc[i][j] = 0.0f;

    for (int k0 = 0; k0 < DD; k0 += 32) {
#pragma unroll
        for (int i = t; i < 64 * 32; i += 256) {
            int r = i >> 5, c = i & 31;
            Xs[r][c] = X[(size_t)(m0 + r) * DD + k0 + c];
            Ws[r][c] = W[(size_t)(n0 + r) * DD + k0 + c];
        }
        __syncthreads();

#pragma unroll
        for (int kk = 0; kk < 32; kk++) {
            float a[4], b[4];
#pragma unroll
            for (int i = 0; i < 4; i++) a[i] = Xs[ty * 4 + i][kk];
#pragma unroll
            for (int j = 0; j < 4; j++) b[j] = Ws[tx * 4 + j][kk];
#pragma unroll
            for (int i = 0; i < 4; i++)
#pragma unroll
                for (int j = 0; j < 4; j++) acc[i][j] += a[i] * b[j];
        }
        __syncthreads();
    }

    // Epilogue: write in [B,H,S,HD] layout with bias.
#pragma unroll
    for (int i = 0; i < 4; i++) {
        int mrow = m0 + ty * 4 + i;
        int b    = mrow >> 11;          // /2048
        int s    = mrow & (SS - 1);
#pragma unroll
        for (int j = 0; j < 4; j++) {
            int jg = n0 + tx * 4 + j;
            int h  = jg / HDIM;
            int d  = jg - h * HDIM;
            outp[(((size_t)(b * HH + h)) * SS + s) * HDIM + d] = acc[i][j] + bias[jg];
        }
    }
}

// ---------------------------------------------------------------------------
// Kernel 2: flash attention with adjacency mask.
// grid = (SS/64, HH, BB), block = 256, dynamic smem ~108KB.
// ---------------------------------------------------------------------------
#define ATTN_SMEM_WORDS (6208 + 6208 + 6144 + 4160 + 64 + 64 + 64 + 4096)
#define ATTN_SMEM_BYTES (ATTN_SMEM_WORDS * 4)

__global__ void __launch_bounds__(256) attn_kernel(const int* __restrict__ adj)
{
    extern __shared__ float sm[];
    float* Qs   = sm;                 // [64][97]
    float* Ks   = Qs + 64 * 97;       // [64][97]
    float* Vs   = Ks + 64 * 97;       // [64][96]  (float4-aligned rows)
    float* Ssm  = Vs + 64 * 96;       // scores/probs transposed [k][q], pitch 65
    float* mrow = Ssm + 64 * 65;      // [64]
    float* lrow = mrow + 64;          // [64]
    float* resc = lrow + 64;          // [64]
    int*   adjs = (int*)(resc + 64);  // [64][64]

    const int t   = threadIdx.x;
    const int qt0 = blockIdx.x * 64;
    const int h   = blockIdx.y;
    const int b   = blockIdx.z;

    const float* __restrict__ Qb = g_QKV[0] + ((size_t)(b * HH + h)) * SS * HDIM;
    const float* __restrict__ Kb = g_QKV[1] + ((size_t)(b * HH + h)) * SS * HDIM;
    const float* __restrict__ Vb = g_QKV[2] + ((size_t)(b * HH + h)) * SS * HDIM;
    const int*   __restrict__ adjb = adj + (size_t)b * SS * SS;

    const float RSQRT_HD = 0.10206207261596577f; // 1/sqrt(96)

    // Load + scale Q tile
#pragma unroll
    for (int i = t; i < 64 * 96; i += 256) {
        int r = i / 96, c = i - r * 96;
        Qs[r * 97 + c] = Qb[(size_t)(qt0 + r) * HDIM + c] * RSQRT_HD;
    }
    if (t < 64) { mrow[t] = -INFINITY; lrow[t] = 0.0f; }

    const int q     = t & 63;
    const int dg    = t >> 6;
    const int dbase = dg * 24;
    float acc[24];
#pragma unroll
    for (int j = 0; j < 24; j++) acc[j] = 0.0f;

    __syncthreads();

    const int tq0 = (t & 15) << 2;
    const int tk0 = (t >> 4) << 2;

    for (int kt0 = 0; kt0 < SS; kt0 += 64) {
        // Stage K, V, adj tiles
#pragma unroll
        for (int i = t; i < 64 * 96; i += 256) {
            int r = i / 96, c = i - r * 96;
            Ks[r * 97 + c] = Kb[(size_t)(kt0 + r) * HDIM + c];
            Vs[r * 96 + c] = Vb[(size_t)(kt0 + r) * HDIM + c];
        }
#pragma unroll
        for (int i = t; i < 64 * 64; i += 256) {
            int r = i >> 6, c = i & 63;
            adjs[i] = adjb[(size_t)(qt0 + r) * SS + kt0 + c];
        }
        __syncthreads();

        // Scores: 4x4 microtile per thread
        {
            float s4[16];
#pragma unroll
            for (int i = 0; i < 16; i++) s4[i] = 0.0f;
#pragma unroll 4
            for (int kk = 0; kk < HDIM; kk++) {
                float a0 = Qs[(tq0 + 0) * 97 + kk];
                float a1 = Qs[(tq0 + 1) * 97 + kk];
                float a2 = Qs[(tq0 + 2) * 97 + kk];
                float a3 = Qs[(tq0 + 3) * 97 + kk];
                float b0 = Ks[(tk0 + 0) * 97 + kk];
                float b1 = Ks[(tk0 + 1) * 97 + kk];
                float b2 = Ks[(tk0 + 2) * 97 + kk];
                float b3 = Ks[(tk0 + 3) * 97 + kk];
                s4[0]  += a0 * b0; s4[1]  += a0 * b1; s4[2]  += a0 * b2; s4[3]  += a0 * b3;
                s4[4]  += a1 * b0; s4[5]  += a1 * b1; s4[6]  += a1 * b2; s4[7]  += a1 * b3;
                s4[8]  += a2 * b0; s4[9]  += a2 * b1; s4[10] += a2 * b2; s4[11] += a2 * b3;
                s4[12] += a3 * b0; s4[13] += a3 * b1; s4[14] += a3 * b2; s4[15] += a3 * b3;
            }
            // Mask and write transposed [k][q]
#pragma unroll
            for (int i = 0; i < 4; i++)
#pragma unroll
                for (int j = 0; j < 4; j++) {
                    float v = s4[i * 4 + j];
                    if (adjs[(tq0 + i) * 64 + (tk0 + j)] == 0) v = -1e9f;
                    Ssm[(tk0 + j) * 65 + (tq0 + i)] = v;
                }
        }
        __syncthreads();

        // Online softmax row update (64 threads)
        if (t < 64) {
            float tm = -1e30f;
#pragma unroll 8
            for (int k = 0; k < 64; k++) tm = fmaxf(tm, Ssm[k * 65 + t]);
            float mold = mrow[t];
            float mnew = fmaxf(mold, tm);
            float sc   = __expf(mold - mnew);   // 0 when mold = -inf
            float sum  = 0.0f;
#pragma unroll 8
            for (int k = 0; k < 64; k++) {
                float p = __expf(Ssm[k * 65 + t] - mnew);
                Ssm[k * 65 + t] = p;
                sum += p;
            }
            lrow[t] = lrow[t] * sc + sum;
            mrow[t] = mnew;
            resc[t] = sc;
        }
        __syncthreads();

        // PV accumulate: thread owns (q, 24 contiguous d)
        {
            float scl = resc[q];
#pragma unroll
            for (int j = 0; j < 24; j++) acc[j] *= scl;
#pragma unroll 4
            for (int k = 0; k < 64; k++) {
                float p = Ssm[k * 65 + q];
                const float4* vp = reinterpret_cast<const float4*>(Vs + k * 96 + dbase);
#pragma unroll
                for (int j4 = 0; j4 < 6; j4++) {
                    float4 vv = vp[j4];
                    acc[j4 * 4 + 0] += p * vv.x;
                    acc[j4 * 4 + 1] += p * vv.y;
                    acc[j4 * 4 + 2] += p * vv.z;
                    acc[j4 * 4 + 3] += p * vv.w;
                }
            }
        }
        __syncthreads();
    }

    // Finalize: normalize, stage via smem for coalesced global write
    {
        float inv = 1.0f / lrow[q];
#pragma unroll
        for (int j = 0; j < 24; j++) Qs[q * 97 + dbase + j] = acc[j] * inv;
    }
    __syncthreads();
#pragma unroll
    for (int i = t; i < 64 * 96; i += 256) {
        int r = i / 96, c = i - r * 96;
        g_C[(size_t)(b * SS + qt0 + r) * DD + h * HDIM + c] = Qs[r * 97 + c];
    }
}

// ---------------------------------------------------------------------------
// Kernel 3: residual + LayerNorm. grid = 16384, block = 256.
// ---------------------------------------------------------------------------
__global__ void __launch_bounds__(256) ln_kernel(
    const float* __restrict__ X,
    const float* __restrict__ gamma,
    const float* __restrict__ beta,
    float* __restrict__ out)
{
    const int row = blockIdx.x;
    const float* __restrict__ c = g_C + (size_t)row * DD;
    const float* __restrict__ x = X  + (size_t)row * DD;
    const int t = threadIdx.x;

    float v[3];
    float sum = 0.0f, sq = 0.0f;
#pragma unroll
    for (int j = 0; j < 3; j++) {
        int idx = t + 256 * j;
        float val = c[idx] + x[idx];
        v[j] = val;
        sum += val;
        sq  += val * val;
    }
#pragma unroll
    for (int o = 16; o > 0; o >>= 1) {
        sum += __shfl_xor_sync(0xFFFFFFFFu, sum, o);
        sq  += __shfl_xor_sync(0xFFFFFFFFu, sq, o);
    }
    __shared__ float rs_[8], rq_[8];
    int w = t >> 5, lane = t & 31;
    if (lane == 0) { rs_[w] = sum; rq_[w] = sq; }
    __syncthreads();
    sum = 0.0f; sq = 0.0f;
#pragma unroll
    for (int w2 = 0; w2 < 8; w2++) { sum += rs_[w2]; sq += rq_[w2]; }

    float mean = sum * (1.0f / 768.0f);
    float var  = sq * (1.0f / 768.0f) - mean * mean;
    float rstd = rsqrtf(var + 1e-5f);
#pragma unroll
    for (int j = 0; j < 3; j++) {
        int idx = t + 256 * j;
        out[(size_t)row * DD + idx] = (v[j] - mean) * rstd * gamma[idx] + beta[idx];
    }
}

// ---------------------------------------------------------------------------
extern "C" void kernel_launch(void* const* d_in, const int* in_sizes, int n_in,
                              void* d_out, int out_size)
{
    const float* X     = (const float*)d_in[0];
    const int*   adj   = (const int*)  d_in[1];
    const float* Wq    = (const float*)d_in[2];
    const float* bq    = (const float*)d_in[3];
    const float* Wk    = (const float*)d_in[4];
    const float* bk    = (const float*)d_in[5];
    const float* Wv    = (const float*)d_in[6];
    const float* bv    = (const float*)d_in[7];
    const float* gamma = (const float*)d_in[8];
    const float* beta  = (const float*)d_in[9];
    float* out = (float*)d_out;

    dim3 gg(DD / 64, M_ROWS / 64, 3);
    qkv_gemm_kernel<<<gg, 256>>>(X, Wq, bq, Wk, bk, Wv, bv);

    cudaFuncSetAttribute(attn_kernel, cudaFuncAttributeMaxDynamicSharedMemorySize,
                         ATTN_SMEM_BYTES);
    dim3 ga(SS / 64, HH, BB);
    attn_kernel<<<ga, 256, ATTN_SMEM_BYTES>>>(adj);

    ln_kernel<<<M_ROWS, 256>>>(X, gamma, beta, out);
}

// round 2
// speedup vs baseline: 3.1635x; 3.1635x over previous
#include <cuda_runtime.h>
#include <math.h>
#include <stdint.h>

#define BB   8
#define SS   2048
#define DD   768
#define HH   8
#define HDIM 96
#define M_ROWS (BB*SS)

// Scratch (allocation-free rule: __device__ globals)
__device__ float g_QKV[3][(size_t)BB*HH*SS*HDIM]; // Q,K,V in [B,H,S,HD]
__device__ float g_C[(size_t)BB*SS*DD];           // attention context [B,S,D]

// ---------------------------------------------------------------------------
// TF32 mma helpers
// ---------------------------------------------------------------------------
__device__ __forceinline__ uint32_t f2tf32(float x) {
    uint32_t r;
    asm("cvt.rna.tf32.f32 %0, %1;" : "=r"(r) : "f"(x));
    return r;
}

__device__ __forceinline__ void mma_tf32(float d[4],
                                         const uint32_t a[4],
                                         const uint32_t b[2]) {
    asm volatile(
        "mma.sync.aligned.m16n8k8.row.col.f32.tf32.tf32.f32 "
        "{%0,%1,%2,%3}, {%4,%5,%6,%7}, {%8,%9}, {%0,%1,%2,%3};\n"
        : "+f"(d[0]), "+f"(d[1]), "+f"(d[2]), "+f"(d[3])
        : "r"(a[0]), "r"(a[1]), "r"(a[2]), "r"(a[3]),
          "r"(b[0]), "r"(b[1]));
}

// ---------------------------------------------------------------------------
// Kernel 1: fused QKV projection via TF32 mma.  Y = X @ W^T + b, out [B,H,S,HD].
// grid = (DD/64, M_ROWS/128, 3), block = 256 (8 warps).
// Block tile 128(M) x 64(N); warp tile 32x32 (2 m16 x 4 n8); K staged 32.
// ---------------------------------------------------------------------------
#define XP 36   // smem pitches: pitch % 32 == 4 -> conflict-free frag loads
#define WP 36

__global__ void __launch_bounds__(256) qkv_gemm_kernel(
    const float* __restrict__ X,
    const float* __restrict__ Wq, const float* __restrict__ bq,
    const float* __restrict__ Wk, const float* __restrict__ bk,
    const float* __restrict__ Wv, const float* __restrict__ bv)
{
    __shared__ float Xs[128 * XP];
    __shared__ float Ws[64 * WP];

    const int z = blockIdx.z;
    const float* __restrict__ W    = (z == 0) ? Wq : ((z == 1) ? Wk : Wv);
    const float* __restrict__ bias = (z == 0) ? bq : ((z == 1) ? bk : bv);
    float* __restrict__ outp = g_QKV[z];

    const int n0 = blockIdx.x * 64;
    const int m0 = blockIdx.y * 128;
    const int t  = threadIdx.x;
    const int w  = t >> 5;
    const int lane = t & 31;
    const int g  = lane >> 2;   // group id (row in frag)
    const int t4 = lane & 3;    // thread-in-group (col in frag)

    const int m0w = (w & 3) * 32;   // warp M offset within tile
    const int n0w = (w >> 2) * 32;  // warp N offset within tile

    float acc[2][4][4];
#pragma unroll
    for (int i = 0; i < 2; i++)
#pragma unroll
        for (int j = 0; j < 4; j++)
#pragma unroll
            for (int e = 0; e < 4; e++) acc[i][j][e] = 0.0f;

    for (int k0 = 0; k0 < DD; k0 += 32) {
        // Stage X tile 128x32 (tf32-converted)
#pragma unroll
        for (int jj = 0; jj < 4; jj++) {
            int e  = t + jj * 256;          // float4 index, 8 per row
            int r  = e >> 3, c4 = (e & 7) * 4;
            float4 v = *reinterpret_cast<const float4*>(
                X + (size_t)(m0 + r) * DD + k0 + c4);
            float* dst = Xs + r * XP + c4;
            dst[0] = __uint_as_float(f2tf32(v.x));
            dst[1] = __uint_as_float(f2tf32(v.y));
            dst[2] = __uint_as_float(f2tf32(v.z));
            dst[3] = __uint_as_float(f2tf32(v.w));
        }
        // Stage W tile 64x32
#pragma unroll
        for (int jj = 0; jj < 2; jj++) {
            int e  = t + jj * 256;
            int r  = e >> 3, c4 = (e & 7) * 4;
            float4 v = *reinterpret_cast<const float4*>(
                W + (size_t)(n0 + r) * DD + k0 + c4);
            float* dst = Ws + r * WP + c4;
            dst[0] = __uint_as_float(f2tf32(v.x));
            dst[1] = __uint_as_float(f2tf32(v.y));
            dst[2] = __uint_as_float(f2tf32(v.z));
            dst[3] = __uint_as_float(f2tf32(v.w));
        }
        __syncthreads();

#pragma unroll
        for (int ks = 0; ks < 4; ks++) {
            const int k = ks * 8;
            uint32_t a[2][4], b[4][2];
#pragma unroll
            for (int i = 0; i < 2; i++) {
                int r = m0w + i * 16 + g;
                a[i][0] = __float_as_uint(Xs[r * XP + k + t4]);
                a[i][1] = __float_as_uint(Xs[(r + 8) * XP + k + t4]);
                a[i][2] = __float_as_uint(Xs[r * XP + k + 4 + t4]);
                a[i][3] = __float_as_uint(Xs[(r + 8) * XP + k + 4 + t4]);
            }
#pragma unroll
            for (int j = 0; j < 4; j++) {
                int n = n0w + j * 8 + g;
                b[j][0] = __float_as_uint(Ws[n * WP + k + t4]);
                b[j][1] = __float_as_uint(Ws[n * WP + k + 4 + t4]);
            }
#pragma unroll
            for (int i = 0; i < 2; i++)
#pragma unroll
                for (int j = 0; j < 4; j++)
                    mma_tf32(acc[i][j], a[i], b[j]);
        }
        __syncthreads();
    }

    // Epilogue: bias + write [B,H,S,HD]
#pragma unroll
    for (int i = 0; i < 2; i++) {
        int rA = m0 + m0w + i * 16 + g;
        int rB = rA + 8;
        int bA = rA >> 11, sA = rA & (SS - 1);
        int bBk = rB >> 11, sB = rB & (SS - 1);
#pragma unroll
        for (int j = 0; j < 4; j++) {
            int c  = n0 + n0w + j * 8 + 2 * t4;  // even, pair stays in one head
            int h  = c / HDIM;
            int d  = c - h * HDIM;
            float2 bi = make_float2(bias[c], bias[c + 1]);
            float2 oA = make_float2(acc[i][j][0] + bi.x, acc[i][j][1] + bi.y);
            float2 oB = make_float2(acc[i][j][2] + bi.x, acc[i][j][3] + bi.y);
            *reinterpret_cast<float2*>(
                outp + (((size_t)(bA * HH + h)) * SS + sA) * HDIM + d) = oA;
            *reinterpret_cast<float2*>(
                outp + (((size_t)(bBk * HH + h)) * SS + sB) * HDIM + d) = oB;
        }
    }
}

// ---------------------------------------------------------------------------
// Kernel 2: flash attention with adjacency mask, TF32 mma for QK^T and PV.
// grid = (SS/64, HH, BB), block = 256 (8 warps).
// ---------------------------------------------------------------------------
#define PQ 100   // %32==4
#define PK 100
#define PV 104   // %32==8 -> 8k+g distinct banks for V B-frags
#define PP 68    // %32==4

#define ATTN_WORDS (64*PQ + 64*PK + 64*PV + 64*PP + 64*3 + 64*64)
#define ATTN_BYTES (ATTN_WORDS * 4)

__global__ void __launch_bounds__(256) attn_kernel(const int* __restrict__ adj)
{
    extern __shared__ float sm[];
    float* Qs   = sm;                  // [64][PQ] tf32 (pre-scaled)
    float* Ks   = Qs + 64 * PQ;        // [64][PK] tf32
    float* Vs   = Ks + 64 * PK;        // [64][PV] tf32
    float* Ps   = Vs + 64 * PV;        // [64][PP] scores -> probs(tf32)
    float* mrow = Ps + 64 * PP;        // [64]
    float* lrow = mrow + 64;           // [64]
    float* resc = lrow + 64;           // [64]
    int*   adjs = (int*)(resc + 64);   // [64][64]

    const int t    = threadIdx.x;
    const int w    = t >> 5;
    const int lane = t & 31;
    const int g    = lane >> 2;
    const int t4   = lane & 3;
    const int qt0  = blockIdx.x * 64;
    const int h    = blockIdx.y;
    const int b    = blockIdx.z;

    const float* __restrict__ Qb = g_QKV[0] + ((size_t)(b * HH + h)) * SS * HDIM;
    const float* __restrict__ Kb = g_QKV[1] + ((size_t)(b * HH + h)) * SS * HDIM;
    const float* __restrict__ Vb = g_QKV[2] + ((size_t)(b * HH + h)) * SS * HDIM;
    const int*   __restrict__ adjb = adj + (size_t)b * SS * SS;

    const float RSQRT_HD = 0.10206207261596577f; // 1/sqrt(96)

    // Warp tiling
    const int m0s = (w & 3) * 16;     // rows (queries) for this warp
    const int n0s = (w >> 2) * 32;    // score cols (keys): 4 n8 tiles
    const int n0v = (w >> 2) * 48;    // output cols (d): 6 n8 tiles
    const int rA  = m0s + g;
    const int rB  = rA + 8;

    // Load + scale + convert Q tile
#pragma unroll
    for (int jj = 0; jj < 6; jj++) {
        int e = t + jj * 256;             // float4 index, 24 per row
        int r = e / 24, c4 = (e % 24) * 4;
        float4 v = *reinterpret_cast<const float4*>(
            Qb + (size_t)(qt0 + r) * HDIM + c4);
        float* dst = Qs + r * PQ + c4;
        dst[0] = __uint_as_float(f2tf32(v.x * RSQRT_HD));
        dst[1] = __uint_as_float(f2tf32(v.y * RSQRT_HD));
        dst[2] = __uint_as_float(f2tf32(v.z * RSQRT_HD));
        dst[3] = __uint_as_float(f2tf32(v.w * RSQRT_HD));
    }
    if (t < 64) { mrow[t] = -INFINITY; lrow[t] = 0.0f; }

    float acc_o[6][4];
#pragma unroll
    for (int j = 0; j < 6; j++)
#pragma unroll
        for (int e = 0; e < 4; e++) acc_o[j][e] = 0.0f;

    __syncthreads();

    for (int kt0 = 0; kt0 < SS; kt0 += 64) {
        // ---- Stage K, V (tf32), adj ----
#pragma unroll
        for (int jj = 0; jj < 6; jj++) {
            int e = t + jj * 256;
            int r = e / 24, c4 = (e % 24) * 4;
            float4 kv = *reinterpret_cast<const float4*>(
                Kb + (size_t)(kt0 + r) * HDIM + c4);
            float4 vv = *reinterpret_cast<const float4*>(
                Vb + (size_t)(kt0 + r) * HDIM + c4);
            float* kd = Ks + r * PK + c4;
            kd[0] = __uint_as_float(f2tf32(kv.x));
            kd[1] = __uint_as_float(f2tf32(kv.y));
            kd[2] = __uint_as_float(f2tf32(kv.z));
            kd[3] = __uint_as_float(f2tf32(kv.w));
            float* vd = Vs + r * PV + c4;
            vd[0] = __uint_as_float(f2tf32(vv.x));
            vd[1] = __uint_as_float(f2tf32(vv.y));
            vd[2] = __uint_as_float(f2tf32(vv.z));
            vd[3] = __uint_as_float(f2tf32(vv.w));
        }
#pragma unroll
        for (int jj = 0; jj < 4; jj++) {
            int e = t + jj * 256;             // int4 index, 16 per row
            int r = e >> 4, c4 = (e & 15) * 4;
            *reinterpret_cast<int4*>(adjs + r * 64 + c4) =
                *reinterpret_cast<const int4*>(
                    adjb + (size_t)(qt0 + r) * SS + kt0 + c4);
        }
        __syncthreads();

        // ---- Scores S = Q K^T (warp: 1 m16 x 4 n8, 12 k-steps) ----
        {
            float acc_s[4][4];
#pragma unroll
            for (int j = 0; j < 4; j++)
#pragma unroll
                for (int e = 0; e < 4; e++) acc_s[j][e] = 0.0f;

#pragma unroll
            for (int ks = 0; ks < 12; ks++) {
                const int k = ks * 8;
                uint32_t a[4], bb[4][2];
                a[0] = __float_as_uint(Qs[rA * PQ + k + t4]);
                a[1] = __float_as_uint(Qs[rB * PQ + k + t4]);
                a[2] = __float_as_uint(Qs[rA * PQ + k + 4 + t4]);
                a[3] = __float_as_uint(Qs[rB * PQ + k + 4 + t4]);
#pragma unroll
                for (int j = 0; j < 4; j++) {
                    int n = n0s + j * 8 + g;
                    bb[j][0] = __float_as_uint(Ks[n * PK + k + t4]);
                    bb[j][1] = __float_as_uint(Ks[n * PK + k + 4 + t4]);
                }
#pragma unroll
                for (int j = 0; j < 4; j++) mma_tf32(acc_s[j], a, bb[j]);
            }

            // Mask + write scores [q][k]
#pragma unroll
            for (int j = 0; j < 4; j++) {
                int c = n0s + j * 8 + 2 * t4;
                float v0 = acc_s[j][0], v1 = acc_s[j][1];
                float v2 = acc_s[j][2], v3 = acc_s[j][3];
                if (adjs[rA * 64 + c] == 0)     v0 = -1e9f;
                if (adjs[rA * 64 + c + 1] == 0) v1 = -1e9f;
                if (adjs[rB * 64 + c] == 0)     v2 = -1e9f;
                if (adjs[rB * 64 + c + 1] == 0) v3 = -1e9f;
                Ps[rA * PP + c]     = v0;
                Ps[rA * PP + c + 1] = v1;
                Ps[rB * PP + c]     = v2;
                Ps[rB * PP + c + 1] = v3;
            }
        }
        __syncthreads();

        // ---- Online softmax: 4 threads per row ----
        {
            int q = t >> 2, part = t & 3;
            float* prow = Ps + q * PP + part * 16;
            float tm = -1e30f;
#pragma unroll
            for (int j = 0; j < 16; j++) tm = fmaxf(tm, prow[j]);
            tm = fmaxf(tm, __shfl_xor_sync(0xFFFFFFFFu, tm, 1));
            tm = fmaxf(tm, __shfl_xor_sync(0xFFFFFFFFu, tm, 2));
            float mold = mrow[q];
            float mnew = fmaxf(mold, tm);
            float sum = 0.0f;
#pragma unroll
            for (int j = 0; j < 16; j++) {
                float p = __expf(prow[j] - mnew);
                sum += p;
                prow[j] = __uint_as_float(f2tf32(p));
            }
            sum += __shfl_xor_sync(0xFFFFFFFFu, sum, 1);
            sum += __shfl_xor_sync(0xFFFFFFFFu, sum, 2);
            if (part == 0) {
                float sc = __expf(mold - mnew);  // 0 when mold == -inf
                mrow[q] = mnew;
                lrow[q] = lrow[q] * sc + sum;
                resc[q] = sc;
            }
        }
        __syncthreads();

        // ---- PV: O += P V (warp: 1 m16 x 6 n8, 8 k-steps) ----
        {
            float s0 = resc[rA], s1 = resc[rB];
#pragma unroll
            for (int j = 0; j < 6; j++) {
                acc_o[j][0] *= s0; acc_o[j][1] *= s0;
                acc_o[j][2] *= s1; acc_o[j][3] *= s1;
            }
#pragma unroll
            for (int ks = 0; ks < 8; ks++) {
                const int k = ks * 8;
                uint32_t a[4], bb[6][2];
                a[0] = __float_as_uint(Ps[rA * PP + k + t4]);
                a[1] = __float_as_uint(Ps[rB * PP + k + t4]);
                a[2] = __float_as_uint(Ps[rA * PP + k + 4 + t4]);
                a[3] = __float_as_uint(Ps[rB * PP + k + 4 + t4]);
#pragma unroll
                for (int j = 0; j < 6; j++) {
                    int n = n0v + j * 8 + g;
                    bb[j][0] = __float_as_uint(Vs[(k + t4) * PV + n]);
                    bb[j][1] = __float_as_uint(Vs[(k + 4 + t4) * PV + n]);
                }
#pragma unroll
                for (int j = 0; j < 6; j++) mma_tf32(acc_o[j], a, bb[j]);
            }
        }
        __syncthreads();
    }

    // ---- Finalize: normalize, write to g_C [B,S,D] ----
    {
        float inv0 = 1.0f / lrow[rA];
        float inv1 = 1.0f / lrow[rB];
#pragma unroll
        for (int j = 0; j < 6; j++) {
            int c = n0v + j * 8 + 2 * t4;   // even
            float2 oA = make_float2(acc_o[j][0] * inv0, acc_o[j][1] * inv0);
            float2 oB = make_float2(acc_o[j][2] * inv1, acc_o[j][3] * inv1);
            *reinterpret_cast<float2*>(
                g_C + (size_t)(b * SS + qt0 + rA) * DD + h * HDIM + c) = oA;
            *reinterpret_cast<float2*>(
                g_C + (size_t)(b * SS + qt0 + rB) * DD + h * HDIM + c) = oB;
        }
    }
}

// ---------------------------------------------------------------------------
// Kernel 3: residual + LayerNorm. grid = 16384, block = 256.
// ---------------------------------------------------------------------------
__global__ void __launch_bounds__(256) ln_kernel(
    const float* __restrict__ X,
    const float* __restrict__ gamma,
    const float* __restrict__ beta,
    float* __restrict__ out)
{
    const int row = blockIdx.x;
    const float* __restrict__ c = g_C + (size_t)row * DD;
    const float* __restrict__ x = X  + (size_t)row * DD;
    const int t = threadIdx.x;

    float v[3];
    float sum = 0.0f, sq = 0.0f;
#pragma unroll
    for (int j = 0; j < 3; j++) {
        int idx = t + 256 * j;
        float val = c[idx] + x[idx];
        v[j] = val;
        sum += val;
        sq  += val * val;
    }
#pragma unroll
    for (int o = 16; o > 0; o >>= 1) {
        sum += __shfl_xor_sync(0xFFFFFFFFu, sum, o);
        sq  += __shfl_xor_sync(0xFFFFFFFFu, sq, o);
    }
    __shared__ float rs_[8], rq_[8];
    int w = t >> 5, lane = t & 31;
    if (lane == 0) { rs_[w] = sum; rq_[w] = sq; }
    __syncthreads();
    sum = 0.0f; sq = 0.0f;
#pragma unroll
    for (int w2 = 0; w2 < 8; w2++) { sum += rs_[w2]; sq += rq_[w2]; }

    float mean = sum * (1.0f / 768.0f);
    float var  = sq * (1.0f / 768.0f) - mean * mean;
    float rstd = rsqrtf(var + 1e-5f);
#pragma unroll
    for (int j = 0; j < 3; j++) {
        int idx = t + 256 * j;
        out[(size_t)row * DD + idx] = (v[j] - mean) * rstd * gamma[idx] + beta[idx];
    }
}

// ---------------------------------------------------------------------------
extern "C" void kernel_launch(void* const* d_in, const int* in_sizes, int n_in,
                              void* d_out, int out_size)
{
    const float* X     = (const float*)d_in[0];
    const int*   adj   = (const int*)  d_in[1];
    const float* Wq    = (const float*)d_in[2];
    const float* bq    = (const float*)d_in[3];
    const float* Wk    = (const float*)d_in[4];
    const float* bk    = (const float*)d_in[5];
    const float* Wv    = (const float*)d_in[6];
    const float* bv    = (const float*)d_in[7];
    const float* gamma = (const float*)d_in[8];
    const float* beta  = (const float*)d_in[9];
    float* out = (float*)d_out;

    dim3 gg(DD / 64, M_ROWS / 128, 3);
    qkv_gemm_kernel<<<gg, 256>>>(X, Wq, bq, Wk, bk, Wv, bv);

    cudaFuncSetAttribute(attn_kernel, cudaFuncAttributeMaxDynamicSharedMemorySize,
                         ATTN_BYTES);
    dim3 ga(SS / 64, HH, BB);
    attn_kernel<<<ga, 256, ATTN_BYTES>>>(adj);

    ln_kernel<<<M_ROWS, 256>>>(X, gamma, beta, out);
}

// round 3
// speedup vs baseline: 4.1502x; 1.3119x over previous
#include <cuda_runtime.h>
#include <math.h>
#include <stdint.h>

#define BB   8
#define SS   2048
#define DD   768
#define HH   8
#define HDIM 96
#define M_ROWS (BB*SS)

// Scratch (allocation-free rule: __device__ globals)
__device__ float g_QKV[3][(size_t)BB*HH*SS*HDIM]; // Q,K,V in [B,H,S,HD]
__device__ float g_C[(size_t)BB*SS*DD];           // attention context [B,S,D]

// ---------------------------------------------------------------------------
// TF32 mma + cp.async helpers. Raw fp32 bits fed to tf32 mma (HW truncates).
// ---------------------------------------------------------------------------
__device__ __forceinline__ void mma_tf32(float d[4],
                                         const uint32_t a[4],
                                         const uint32_t b[2]) {
    asm volatile(
        "mma.sync.aligned.m16n8k8.row.col.f32.tf32.tf32.f32 "
        "{%0,%1,%2,%3}, {%4,%5,%6,%7}, {%8,%9}, {%0,%1,%2,%3};\n"
        : "+f"(d[0]), "+f"(d[1]), "+f"(d[2]), "+f"(d[3])
        : "r"(a[0]), "r"(a[1]), "r"(a[2]), "r"(a[3]),
          "r"(b[0]), "r"(b[1]));
}

__device__ __forceinline__ void cp16(uint32_t dst, const void* src) {
    asm volatile("cp.async.cg.shared.global [%0], [%1], 16;\n"
                 :: "r"(dst), "l"(src));
}
__device__ __forceinline__ void cp_commit() {
    asm volatile("cp.async.commit_group;\n");
}
__device__ __forceinline__ void cp_wait1() {
    asm volatile("cp.async.wait_group 1;\n");
}
__device__ __forceinline__ void cp_wait0() {
    asm volatile("cp.async.wait_group 0;\n");
}

// ---------------------------------------------------------------------------
// Kernel 1: fused QKV projection. Y = X @ W^T + b, out [B,H,S,HD].
// Block tile 128x128, k-stage 32, 2-stage cp.async. 8 warps, warp 32x64.
// grid = (DD/128, M_ROWS/128, 3), block 256.
// ---------------------------------------------------------------------------
#define GP 36            // smem pitch (%32==4 -> conflict-free frag loads)
#define G_STAGE (128*GP) // words per tile buffer
#define G_BYTES (4 * 4 * G_STAGE)  // 2 arrays x 2 stages

__global__ void __launch_bounds__(256, 2) qkv_gemm_kernel(
    const float* __restrict__ X,
    const float* __restrict__ Wq, const float* __restrict__ bq,
    const float* __restrict__ Wk, const float* __restrict__ bk,
    const float* __restrict__ Wv, const float* __restrict__ bv)
{
    extern __shared__ float gsm[];
    float* Xs = gsm;                 // [2][128][GP]
    float* Ws = gsm + 2 * G_STAGE;   // [2][128][GP]
    const uint32_t smb = (uint32_t)__cvta_generic_to_shared(gsm);

    const int z = blockIdx.z;
    const float* __restrict__ W    = (z == 0) ? Wq : ((z == 1) ? Wk : Wv);
    const float* __restrict__ bias = (z == 0) ? bq : ((z == 1) ? bk : bv);
    float* __restrict__ outp = g_QKV[z];

    const int n0 = blockIdx.x * 128;
    const int m0 = blockIdx.y * 128;
    const int t  = threadIdx.x;
    const int w  = t >> 5;
    const int lane = t & 31;
    const int g  = lane >> 2;
    const int t4 = lane & 3;

    const int m0w = (w & 3) * 32;
    const int n0w = (w >> 2) * 64;

    // staging: each thread copies 4 float4 of X and 4 of W per stage
    const int sr = t >> 1;                 // row 0..127
    const int sc = (t & 1) * 16;           // col 0 or 16 (two float4 pairs)

    auto issue = [&](int k0, int buf) {
        uint32_t xb = smb + (buf * G_STAGE) * 4;
        uint32_t wb = smb + ((2 + buf) * G_STAGE) * 4;
#pragma unroll
        for (int i = 0; i < 2; i++) {
            int c4 = sc + i * 8;           // 0,8 or 16,24
            cp16(xb + (sr * GP + c4) * 4, X + (size_t)(m0 + sr) * DD + k0 + c4);
            cp16(xb + (sr * GP + c4 + 4) * 4, X + (size_t)(m0 + sr) * DD + k0 + c4 + 4);
            cp16(wb + (sr * GP + c4) * 4, W + (size_t)(n0 + sr) * DD + k0 + c4);
            cp16(wb + (sr * GP + c4 + 4) * 4, W + (size_t)(n0 + sr) * DD + k0 + c4 + 4);
        }
        cp_commit();
    };

    float acc[2][8][4];
#pragma unroll
    for (int i = 0; i < 2; i++)
#pragma unroll
        for (int j = 0; j < 8; j++)
#pragma unroll
            for (int e = 0; e < 4; e++) acc[i][j][e] = 0.0f;

    issue(0, 0);

    const int NIT = DD / 32;  // 24
    for (int it = 0; it < NIT; it++) {
        if (it + 1 < NIT) { issue((it + 1) * 32, (it + 1) & 1); cp_wait1(); }
        else              { cp_wait0(); }
        __syncthreads();

        const float* xs = Xs + (it & 1) * G_STAGE;
        const float* ws = Ws + (2 + (it & 1) - 2) * G_STAGE + 2 * G_STAGE; // Ws base
        ws = Ws + (it & 1) * G_STAGE;

#pragma unroll
        for (int ks = 0; ks < 4; ks++) {
            const int k = ks * 8;
            uint32_t a[2][4];
#pragma unroll
            for (int i = 0; i < 2; i++) {
                int r = m0w + i * 16 + g;
                a[i][0] = __float_as_uint(xs[r * GP + k + t4]);
                a[i][1] = __float_as_uint(xs[(r + 8) * GP + k + t4]);
                a[i][2] = __float_as_uint(xs[r * GP + k + 4 + t4]);
                a[i][3] = __float_as_uint(xs[(r + 8) * GP + k + 4 + t4]);
            }
#pragma unroll
            for (int j = 0; j < 8; j++) {
                uint32_t b[2];
                int n = n0w + j * 8 + g;
                b[0] = __float_as_uint(ws[n * GP + k + t4]);
                b[1] = __float_as_uint(ws[n * GP + k + 4 + t4]);
#pragma unroll
                for (int i = 0; i < 2; i++) mma_tf32(acc[i][j], a[i], b);
            }
        }
        __syncthreads();
    }

    // Epilogue: bias + write [B,H,S,HD]
#pragma unroll
    for (int i = 0; i < 2; i++) {
        int rA = m0 + m0w + i * 16 + g;
        int rB = rA + 8;
        int bA = rA >> 11, sA = rA & (SS - 1);
        int bBk = rB >> 11, sB = rB & (SS - 1);
#pragma unroll
        for (int j = 0; j < 8; j++) {
            int c = n0 + n0w + j * 8 + 2 * t4;   // even -> pair in one head
            int h = c / HDIM;
            int d = c - h * HDIM;
            float2 bi = make_float2(bias[c], bias[c + 1]);
            float2 oA = make_float2(acc[i][j][0] + bi.x, acc[i][j][1] + bi.y);
            float2 oB = make_float2(acc[i][j][2] + bi.x, acc[i][j][3] + bi.y);
            *reinterpret_cast<float2*>(
                outp + (((size_t)(bA * HH + h)) * SS + sA) * HDIM + d) = oA;
            *reinterpret_cast<float2*>(
                outp + (((size_t)(bBk * HH + h)) * SS + sB) * HDIM + d) = oB;
        }
    }
}

// ---------------------------------------------------------------------------
// Kernel 2: FA2-style flash attention, adjacency mask, TF32 mma.
// CTA = 128 queries; warp owns 16 rows (softmax state in registers).
// K/V/adj 2-stage cp.async. grid = (SS/128, HH, BB), block 256.
// ---------------------------------------------------------------------------
#define PK  100  // %32==4
#define PVp 104  // %32==8
#define PA  68   // adj pitch (ints), 272B rows, 16B-aligned
#define PP  68   // probs pitch
#define QT  128
#define KT  64
#define NKT (SS / KT)

#define ST_K (64 * PK)
#define ST_V (64 * PVp)
#define ST_A (QT * PA)
#define ST_WORDS (ST_K + ST_V + ST_A)
#define ATTN_BYTES ((2 * ST_WORDS + QT * PP) * 4)

__global__ void __launch_bounds__(256, 1) attn_kernel(const int* __restrict__ adj)
{
    extern __shared__ float sm[];
    float* Ps = sm + 2 * ST_WORDS;            // [128][PP]
    const uint32_t smb = (uint32_t)__cvta_generic_to_shared(sm);

    const int t    = threadIdx.x;
    const int w    = t >> 5;
    const int lane = t & 31;
    const int g    = lane >> 2;
    const int t4   = lane & 3;
    const int qt0  = blockIdx.x * QT;
    const int h    = blockIdx.y;
    const int b    = blockIdx.z;

    const float* __restrict__ Qb = g_QKV[0] + ((size_t)(b * HH + h)) * SS * HDIM;
    const float* __restrict__ Kb = g_QKV[1] + ((size_t)(b * HH + h)) * SS * HDIM;
    const float* __restrict__ Vb = g_QKV[2] + ((size_t)(b * HH + h)) * SS * HDIM;
    const int*   __restrict__ adjb = adj + (size_t)b * SS * SS;

    const int rAl = 16 * w + g;   // local q rows owned by this thread
    const int rBl = rAl + 8;

    // ---- Preload Q fragments to registers (scaled by 1/sqrt(HD)) ----
    const float RS = 0.10206207261596577f;
    uint32_t qa[12][4];
    {
        const float* qA = Qb + (size_t)(qt0 + rAl) * HDIM;
        const float* qB = Qb + (size_t)(qt0 + rBl) * HDIM;
#pragma unroll
        for (int ks = 0; ks < 12; ks++) {
            qa[ks][0] = __float_as_uint(qA[8 * ks + t4] * RS);
            qa[ks][1] = __float_as_uint(qB[8 * ks + t4] * RS);
            qa[ks][2] = __float_as_uint(qA[8 * ks + 4 + t4] * RS);
            qa[ks][3] = __float_as_uint(qB[8 * ks + 4 + t4] * RS);
        }
    }

    float acc_o[12][4];
#pragma unroll
    for (int j = 0; j < 12; j++)
#pragma unroll
        for (int e = 0; e < 4; e++) acc_o[j][e] = 0.0f;
    float m0_ = -INFINITY, m1_ = -INFINITY, l0_ = 0.0f, l1_ = 0.0f;

    // ---- staging ----
    auto issue = [&](int kt0, int buf) {
        uint32_t sb = smb + (buf * ST_WORDS) * 4;
#pragma unroll
        for (int i = 0; i < 6; i++) {
            int e = t + i * 256;
            int r = e / 24, c4 = (e % 24) * 4;
            cp16(sb + (r * PK + c4) * 4, Kb + (size_t)(kt0 + r) * HDIM + c4);
            cp16(sb + ((ST_K + r * PVp) + c4) * 4, Vb + (size_t)(kt0 + r) * HDIM + c4);
        }
#pragma unroll
        for (int i = 0; i < 8; i++) {
            int e = t + i * 256;
            int r = e >> 4, c4 = (e & 15) * 4;
            cp16(sb + ((ST_K + ST_V) + r * PA + c4) * 4,
                 adjb + (size_t)(qt0 + r) * SS + kt0 + c4);
        }
        cp_commit();
    };

    issue(0, 0);

    for (int kt = 0; kt < NKT; kt++) {
        if (kt + 1 < NKT) { issue((kt + 1) * KT, (kt + 1) & 1); cp_wait1(); }
        else              { cp_wait0(); }
        __syncthreads();

        const float* Ks_ = sm + (kt & 1) * ST_WORDS;
        const float* Vs_ = Ks_ + ST_K;
        const int*   adjs = (const int*)(Vs_ + ST_V);

        // ---- S = Q K^T : warp computes its 16 rows x all 64 keys ----
        float s_[8][4];
#pragma unroll
        for (int j = 0; j < 8; j++)
#pragma unroll
            for (int e = 0; e < 4; e++) s_[j][e] = 0.0f;

#pragma unroll
        for (int ks = 0; ks < 12; ks++) {
            const int k = ks * 8;
#pragma unroll
            for (int j = 0; j < 8; j++) {
                uint32_t bkf[2];
                int n = j * 8 + g;
                bkf[0] = __float_as_uint(Ks_[n * PK + k + t4]);
                bkf[1] = __float_as_uint(Ks_[n * PK + k + 4 + t4]);
                mma_tf32(s_[j], qa[ks], bkf);
            }
        }

        // ---- mask + register online softmax ----
        float tmax0 = -1e30f, tmax1 = -1e30f;
#pragma unroll
        for (int j = 0; j < 8; j++) {
            int2 mA = *(const int2*)(adjs + rAl * PA + 8 * j + 2 * t4);
            int2 mB = *(const int2*)(adjs + rBl * PA + 8 * j + 2 * t4);
            if (mA.x == 0) s_[j][0] = -1e9f;
            if (mA.y == 0) s_[j][1] = -1e9f;
            if (mB.x == 0) s_[j][2] = -1e9f;
            if (mB.y == 0) s_[j][3] = -1e9f;
            tmax0 = fmaxf(tmax0, fmaxf(s_[j][0], s_[j][1]));
            tmax1 = fmaxf(tmax1, fmaxf(s_[j][2], s_[j][3]));
        }
        tmax0 = fmaxf(tmax0, __shfl_xor_sync(0xFFFFFFFFu, tmax0, 1));
        tmax0 = fmaxf(tmax0, __shfl_xor_sync(0xFFFFFFFFu, tmax0, 2));
        tmax1 = fmaxf(tmax1, __shfl_xor_sync(0xFFFFFFFFu, tmax1, 1));
        tmax1 = fmaxf(tmax1, __shfl_xor_sync(0xFFFFFFFFu, tmax1, 2));

        float mn0 = fmaxf(m0_, tmax0), mn1 = fmaxf(m1_, tmax1);
        float sc0 = __expf(m0_ - mn0),  sc1 = __expf(m1_ - mn1);
        m0_ = mn0; m1_ = mn1;

        float sum0 = 0.0f, sum1 = 0.0f;
#pragma unroll
        for (int j = 0; j < 8; j++) {
            float p0 = __expf(s_[j][0] - mn0);
            float p1 = __expf(s_[j][1] - mn0);
            float p2 = __expf(s_[j][2] - mn1);
            float p3 = __expf(s_[j][3] - mn1);
            sum0 += p0 + p1; sum1 += p2 + p3;
            *reinterpret_cast<float2*>(Ps + rAl * PP + 8 * j + 2 * t4) = make_float2(p0, p1);
            *reinterpret_cast<float2*>(Ps + rBl * PP + 8 * j + 2 * t4) = make_float2(p2, p3);
        }
        sum0 += __shfl_xor_sync(0xFFFFFFFFu, sum0, 1);
        sum0 += __shfl_xor_sync(0xFFFFFFFFu, sum0, 2);
        sum1 += __shfl_xor_sync(0xFFFFFFFFu, sum1, 1);
        sum1 += __shfl_xor_sync(0xFFFFFFFFu, sum1, 2);
        l0_ = l0_ * sc0 + sum0;
        l1_ = l1_ * sc1 + sum1;

#pragma unroll
        for (int j = 0; j < 12; j++) {
            acc_o[j][0] *= sc0; acc_o[j][1] *= sc0;
            acc_o[j][2] *= sc1; acc_o[j][3] *= sc1;
        }
        __syncwarp();   // P write -> P read, warp-private rows

        // ---- O += P V : 12 n8 tiles (96 d), 8 k-steps ----
#pragma unroll
        for (int ks = 0; ks < 8; ks++) {
            const int k = ks * 8;
            uint32_t a[4];
            a[0] = __float_as_uint(Ps[rAl * PP + k + t4]);
            a[1] = __float_as_uint(Ps[rBl * PP + k + t4]);
            a[2] = __float_as_uint(Ps[rAl * PP + k + 4 + t4]);
            a[3] = __float_as_uint(Ps[rBl * PP + k + 4 + t4]);
#pragma unroll
            for (int j = 0; j < 12; j++) {
                uint32_t bv_[2];
                int n = j * 8 + g;
                bv_[0] = __float_as_uint(Vs_[(k + t4) * PVp + n]);
                bv_[1] = __float_as_uint(Vs_[(k + 4 + t4) * PVp + n]);
                mma_tf32(acc_o[j], a, bv_);
            }
        }
        __syncthreads();
    }

    // ---- finalize ----
    {
        float inv0 = 1.0f / l0_;
        float inv1 = 1.0f / l1_;
        float* oA = g_C + (size_t)(b * SS + qt0 + rAl) * DD + h * HDIM;
        float* oB = g_C + (size_t)(b * SS + qt0 + rBl) * DD + h * HDIM;
#pragma unroll
        for (int j = 0; j < 12; j++) {
            int c = j * 8 + 2 * t4;
            *reinterpret_cast<float2*>(oA + c) =
                make_float2(acc_o[j][0] * inv0, acc_o[j][1] * inv0);
            *reinterpret_cast<float2*>(oB + c) =
                make_float2(acc_o[j][2] * inv1, acc_o[j][3] * inv1);
        }
    }
}

// ---------------------------------------------------------------------------
// Kernel 3: residual + LayerNorm. grid = 16384, block = 256.
// ---------------------------------------------------------------------------
__global__ void __launch_bounds__(256) ln_kernel(
    const float* __restrict__ X,
    const float* __restrict__ gamma,
    const float* __restrict__ beta,
    float* __restrict__ out)
{
    const int row = blockIdx.x;
    const float* __restrict__ c = g_C + (size_t)row * DD;
    const float* __restrict__ x = X  + (size_t)row * DD;
    const int t = threadIdx.x;

    float v[3];
    float sum = 0.0f, sq = 0.0f;
#pragma unroll
    for (int j = 0; j < 3; j++) {
        int idx = t + 256 * j;
        float val = c[idx] + x[idx];
        v[j] = val;
        sum += val;
        sq  += val * val;
    }
#pragma unroll
    for (int o = 16; o > 0; o >>= 1) {
        sum += __shfl_xor_sync(0xFFFFFFFFu, sum, o);
        sq  += __shfl_xor_sync(0xFFFFFFFFu, sq, o);
    }
    __shared__ float rs_[8], rq_[8];
    int w = t >> 5, lane = t & 31;
    if (lane == 0) { rs_[w] = sum; rq_[w] = sq; }
    __syncthreads();
    sum = 0.0f; sq = 0.0f;
#pragma unroll
    for (int w2 = 0; w2 < 8; w2++) { sum += rs_[w2]; sq += rq_[w2]; }

    float mean = sum * (1.0f / 768.0f);
    float var  = sq * (1.0f / 768.0f) - mean * mean;
    float rstd = rsqrtf(var + 1e-5f);
#pragma unroll
    for (int j = 0; j < 3; j++) {
        int idx = t + 256 * j;
        out[(size_t)row * DD + idx] = (v[j] - mean) * rstd * gamma[idx] + beta[idx];
    }
}

// ---------------------------------------------------------------------------
extern "C" void kernel_launch(void* const* d_in, const int* in_sizes, int n_in,
                              void* d_out, int out_size)
{
    const float* X     = (const float*)d_in[0];
    const int*   adj   = (const int*)  d_in[1];
    const float* Wq    = (const float*)d_in[2];
    const float* bq    = (const float*)d_in[3];
    const float* Wk    = (const float*)d_in[4];
    const float* bk    = (const float*)d_in[5];
    const float* Wv    = (const float*)d_in[6];
    const float* bv    = (const float*)d_in[7];
    const float* gamma = (const float*)d_in[8];
    const float* beta  = (const float*)d_in[9];
    float* out = (float*)d_out;

    cudaFuncSetAttribute(qkv_gemm_kernel,
                         cudaFuncAttributeMaxDynamicSharedMemorySize, G_BYTES);
    dim3 gg(DD / 128, M_ROWS / 128, 3);
    qkv_gemm_kernel<<<gg, 256, G_BYTES>>>(X, Wq, bq, Wk, bk, Wv, bv);

    cudaFuncSetAttribute(attn_kernel,
                         cudaFuncAttributeMaxDynamicSharedMemorySize, ATTN_BYTES);
    dim3 ga(SS / QT, HH, BB);
    attn_kernel<<<ga, 256, ATTN_BYTES>>>(adj);

    ln_kernel<<<M_ROWS, 256>>>(X, gamma, beta, out);
}